// round 16
// baseline (speedup 1.0000x reference)
#include <cuda_runtime.h>
#include <math.h>

#define TT 1024
#define BB 32
#define DD 1024
#define BD (BB*DD)          /* 32768    */
#define TBD (TT*BB*DD)      /* 33554432 */

/* ---------- packed f32x2 helpers (sm_103a FFMA2) ---------- */
__device__ __forceinline__ void fma2(unsigned long long& acc,
                                     unsigned long long a,
                                     unsigned long long b) {
    asm("fma.rn.f32x2 %0, %1, %2, %0;" : "+l"(acc) : "l"(a), "l"(b));
}
__device__ __forceinline__ unsigned long long pack2(float lo, float hi) {
    unsigned long long r;
    asm("mov.b64 %0, {%1, %2};" : "=l"(r)
        : "r"(__float_as_uint(lo)), "r"(__float_as_uint(hi)));
    return r;
}
__device__ __forceinline__ float lo32(unsigned long long v) {
    return __uint_as_float((unsigned int)(v & 0xffffffffull));
}
__device__ __forceinline__ float hi32(unsigned long long v) {
    return __uint_as_float((unsigned int)(v >> 32));
}
__device__ __forceinline__ float tanh_fast(float x) {
    float y;
    asm("tanh.approx.f32 %0, %1;" : "=f"(y) : "f"(x));
    return y;
}

/* transposed hidden state, double-buffered, k-paired:
 * g_hT2[par][k2][b][kpar]  (float2 per (k2,b)) — 256 KB static        */
__device__ float g_hT2[2][DD/2][BB][2];

/* per-phase barrier state: counters and gen words, 128B apart         */
__device__ unsigned int g_pc[2 * 32];   /* arrival counters  */
__device__ unsigned int g_pg[2 * 32];   /* monotonic gens    */
/* init barrier (R6-proven) */
__device__ unsigned int g_bar = 0;
__device__ unsigned int g_gen = 0;

/* ================= precompute GEMM (FFMA2) — unchanged ================= */
#define BM 64
#define BN 64
#define BKK 16
#define PAD 72

__global__ __launch_bounds__(256) void pre_gemm_kernel(
    const float* __restrict__ x,
    const float* __restrict__ Rx,
    const float* __restrict__ Wdl,
    const float* __restrict__ bias_v,
    const float* __restrict__ bias_d,
    float* __restrict__ outsec,
    float* __restrict__ hsec)
{
    __shared__ float As[BKK][PAD];
    __shared__ unsigned long long Wp[BKK][BN];

    const int m0  = blockIdx.x * BM;
    const int n0g = blockIdx.y * BN;
    const int sel = (n0g >= DD) ? 1 : 0;
    const float* __restrict__ W    = sel ? Wdl    : Rx;
    const float* __restrict__ bias = sel ? bias_d : bias_v;
    float* __restrict__ dst = sel ? (hsec + BD) : outsec;
    const int n0 = n0g & (DD - 1);

    const int tid  = threadIdx.x;
    const int lrow = tid >> 2;
    const int lk4  = (tid & 3) * 4;
    const int tx   = tid & 15;
    const int ty   = tid >> 4;

    unsigned long long acc2[2][4];
    #pragma unroll
    for (int p = 0; p < 2; p++)
        #pragma unroll
        for (int j = 0; j < 4; j++) acc2[p][j] = 0ull;

    const float* xa = x + (size_t)(m0 + lrow) * DD;
    const float* wa = W + (size_t)(n0 + lrow) * DD;

    for (int kk = 0; kk < DD; kk += BKK) {
        float4 a4 = *(const float4*)(xa + kk + lk4);
        float4 w4 = *(const float4*)(wa + kk + lk4);
        As[lk4 + 0][lrow] = a4.x; As[lk4 + 1][lrow] = a4.y;
        As[lk4 + 2][lrow] = a4.z; As[lk4 + 3][lrow] = a4.w;
        Wp[lk4 + 0][lrow] = pack2(w4.x, w4.x);
        Wp[lk4 + 1][lrow] = pack2(w4.y, w4.y);
        Wp[lk4 + 2][lrow] = pack2(w4.z, w4.z);
        Wp[lk4 + 3][lrow] = pack2(w4.w, w4.w);
        __syncthreads();

        #pragma unroll
        for (int k = 0; k < BKK; k++) {
            ulonglong2 a2 = *(const ulonglong2*)&As[k][ty * 4];
            ulonglong2 wA = *(const ulonglong2*)&Wp[k][tx * 4];
            ulonglong2 wB = *(const ulonglong2*)&Wp[k][tx * 4 + 2];
            fma2(acc2[0][0], a2.x, wA.x); fma2(acc2[0][1], a2.x, wA.y);
            fma2(acc2[0][2], a2.x, wB.x); fma2(acc2[0][3], a2.x, wB.y);
            fma2(acc2[1][0], a2.y, wA.x); fma2(acc2[1][1], a2.y, wA.y);
            fma2(acc2[1][2], a2.y, wB.x); fma2(acc2[1][3], a2.y, wB.y);
        }
        __syncthreads();
    }

    #pragma unroll
    for (int p = 0; p < 2; p++) {
        #pragma unroll
        for (int j = 0; j < 4; j++) {
            const int col = n0 + tx * 4 + j;
            const float bb = bias[col];
            dst[(size_t)(m0 + ty * 4 + 2 * p + 0) * DD + col] = lo32(acc2[p][j]) + bb;
            dst[(size_t)(m0 + ty * 4 + 2 * p + 1) * DD + col] = hi32(acc2[p][j]) + bb;
        }
    }
}

/* ================= persistent recurrence: phase-split (b-halves) ======= */
#define SMEM_W  (DD * 8 * 8)        /* 65536 B packed weight pairs       */
#define SMEM_P  (4 * 8 * 32 * 8)    /*  8192 B partials: [q][w][lane]    */
#define SMEM_REC (SMEM_W + SMEM_P)

__device__ __forceinline__ void init_grid_sync() {
    __syncthreads();
    if (threadIdx.x == 0) {
        __threadfence();
        unsigned int gen = *((volatile unsigned int*)&g_gen);
        if (atomicAdd(&g_bar, 1) == 127u) {
            atomicExch(&g_bar, 0);
            __threadfence();
            atomicAdd(&g_gen, 1);
        } else {
            while (*((volatile unsigned int*)&g_gen) == gen) __nanosleep(32);
        }
        __threadfence();
    }
    __syncthreads();
}

/* one group = 4 float2 = 8 k values */
#define PGROUP(bank, g, pf)                                                  \
    {                                                                        \
        _Pragma("unroll")                                                    \
        for (int i = 0; i < 4; i++) {                                        \
            float2 hv = bank[i];                                             \
            if (pf) bank[i] = __ldg(hcol2 + ((g) + 2) * 4 * 32 + i * 32);    \
            unsigned long long hXa = pack2(hv.x, hv.x);                      \
            unsigned long long hXb = pack2(hv.y, hv.y);                      \
            const int kk = kb + ((g) * 4 + i) * 2;                           \
            ulonglong2 wva = *(const ulonglong2*)&sWp[kk * 8 + dh2w];        \
            ulonglong2 wda = *(const ulonglong2*)&sWp[kk * 8 + 4 + dh2w];    \
            ulonglong2 wvb = *(const ulonglong2*)&sWp[(kk + 1) * 8 + dh2w];  \
            ulonglong2 wdb = *(const ulonglong2*)&sWp[(kk + 1) * 8 + 4 + dh2w];\
            fma2(a00, wva.x, hXa); fma2(a01, wva.y, hXa);                    \
            fma2(a10, wda.x, hXa); fma2(a11, wda.y, hXa);                    \
            fma2(a00, wvb.x, hXb); fma2(a01, wvb.y, hXb);                    \
            fma2(a10, wdb.x, hXb); fma2(a11, wdb.y, hXb);                    \
        }                                                                    \
    }

__global__ __launch_bounds__(256, 1) void rec_kernel(
    const float* __restrict__ x,
    const float* __restrict__ h0,
    const float* __restrict__ Rh,
    const float* __restrict__ Rd,
    const float* __restrict__ bgate,
    float* __restrict__ outsec,
    float* __restrict__ hsec)
{
    extern __shared__ unsigned char smem[];
    unsigned long long* sWp = (unsigned long long*)smem;        /* [k][8]  */
    unsigned long long* sP  = (unsigned long long*)(smem + SMEM_W);
    const float* sPf = (const float*)sP;

    const int cta  = blockIdx.x;
    const int d0   = cta * 8;
    const int tid  = threadIdx.x;
    const int w    = tid >> 5;
    const int lane = tid & 31;
    const int bl   = lane & 15;      /* b-local within phase   */
    const int dh   = lane >> 4;      /* d-half: 0 -> d0..3, 1 -> d4..7 */
    const int dh2w = dh * 2;
    const int kb   = w * 128;        /* this warp's k range    */

    /* replay bases for the two phase gens (before any arrival possible) */
    const unsigned int gb0 = *((volatile unsigned int*)&g_pg[0]);
    const unsigned int gb1 = *((volatile unsigned int*)&g_pg[32]);

    /* ---- stage packed weight pairs into smem (once, unchanged) ---- */
    #pragma unroll
    for (int m = 0; m < 2; m++) {
        const float* W = m ? Rd : Rh;
        #pragma unroll
        for (int p = 0; p < 4; p++) {
            const float* r0 = W + (size_t)(d0 + 2 * p)     * DD;
            const float* r1 = W + (size_t)(d0 + 2 * p + 1) * DD;
            for (int k = tid; k < DD; k += 256)
                sWp[k * 8 + m * 4 + p] = pack2(r0[k], r1[k]);
        }
    }

    /* ---- init h[0] in k-paired layout: CTA owns k rows 8c..8c+8 ---- */
    {
        const int k = 8 * cta + w;
        g_hT2[0][k >> 1][lane][k & 1] = h0[(size_t)lane * DD + k];
    }

    /* epilogue identity: tid<128 owns (ebl, ed) in each phase */
    const int ebl = (tid >> 3) & 15;
    const int ed  = tid & 7;
    const float bgv = bgate[d0 + ed];
    const int edh = ed >> 2, ej = (ed >> 1) & 1, ee = ed & 1;
    const int eln = ebl + 16 * edh;

    float hp[2];
    if (tid < 128) {
        hp[0] = h0[(size_t)(ebl)      * DD + d0 + ed];
        hp[1] = h0[(size_t)(16 + ebl) * DD + d0 + ed];
    }

    init_grid_sync();   /* h[0] + bases everywhere; weights staged */

    for (int t = 0; t < TT; t++) {
        const int cur = t & 1, nxt = cur ^ 1;

        #pragma unroll
        for (int bg = 0; bg < 2; bg++) {
            /* stash prefetch — thread-private addresses, legal pre-wait */
            const size_t idxp = (size_t)t * BD
                              + (size_t)(bg * 16 + ebl) * DD + d0 + ed;
            float pf_v = 0.f, pf_d = 0.f, pf_x = 0.f;
            if (tid < 128) {
                pf_v = outsec[idxp];
                pf_d = hsec[idxp + BD];
                pf_x = x[idxp];
            }

            /* wait: h[t] for this b-half published (gen[bg] >= t) */
            if (t > 0 && tid == 0) {
                const unsigned int base = bg ? gb1 : gb0;
                while ((int)(*((volatile unsigned int*)&g_pg[bg * 32]) - base)
                       < t)
                    __nanosleep(32);
                __threadfence();
            }
            __syncthreads();

            const float2* hcol2 = (const float2*)g_hT2
                + ((size_t)cur * (DD / 2) + w * 64) * BB + bg * 16 + bl;

            unsigned long long a00 = 0, a01 = 0, a10 = 0, a11 = 0;

            float2 hA[4], hB[4];
            #pragma unroll
            for (int i = 0; i < 4; i++) {
                hA[i] = __ldg(hcol2 + i * 32);
                hB[i] = __ldg(hcol2 + (4 + i) * 32);
            }

            #pragma unroll 2
            for (int g2 = 0; g2 < 8; g2++) {
                PGROUP(hA, g2 * 2,     g2 < 7)
                PGROUP(hB, g2 * 2 + 1, g2 < 7)
            }

            /* partials: sP[q][w][lane], q = m*2 + j (conflict-free STS64) */
            sP[0 * 256 + w * 32 + lane] = a00;
            sP[1 * 256 + w * 32 + lane] = a01;
            sP[2 * 256 + w * 32 + lane] = a10;
            sP[3 * 256 + w * 32 + lane] = a11;
            __syncthreads();

            /* ---- epilogue: tid<128 -> (b = bg*16+ebl, d = d0+ed) ---- */
            if (tid < 128) {
                float sumv = 0.f, sumd = 0.f;
                #pragma unroll
                for (int w8 = 0; w8 < 8; w8++) {
                    sumv += sPf[((ej)     * 256 + w8 * 32 + eln) * 2 + ee];
                    sumd += sPf[((2 + ej) * 256 + w8 * 32 + eln) * 2 + ee];
                }
                const float v     = pf_v + sumv;
                const float dpre  = pf_d + sumd;
                const float delta = 1.f / (1.f + __expf(-dpre));
                const float hn    = (1.f - delta) * hp[bg]
                                  + delta * tanh_fast(v);
                const float z     = hn + pf_x + bgv;
                const float sig   = 1.f / (1.f + __expf(-z));

                outsec[idxp]      = hn * z * sig;     /* out[t]          */
                hsec[idxp + BD]   = hn;               /* h[t+1] (output) */
                g_hT2[nxt][(d0 + ed) >> 1][bg * 16 + ebl][(d0 + ed) & 1] = hn;
                hp[bg] = hn;
            }
            __syncthreads();   /* g_hT2 writes done; sP reusable */

            /* arrive for (t, bg): non-blocking publish */
            if (t + 1 < TT && tid == 0) {
                __threadfence();
                if (atomicAdd(&g_pc[bg * 32], 1u) == 127u) {
                    atomicExch(&g_pc[bg * 32], 0u);
                    __threadfence();
                    atomicAdd(&g_pg[bg * 32], 1u);
                }
            }
        }
    }
}

extern "C" void kernel_launch(void* const* d_in, const int* in_sizes, int n_in,
                              void* d_out, int out_size)
{
    const float* x   = (const float*)d_in[0];
    const float* h0  = (const float*)d_in[1];
    const float* Rh  = (const float*)d_in[2];
    const float* Rx  = (const float*)d_in[3];
    const float* Rd  = (const float*)d_in[4];
    const float* Wdl = (const float*)d_in[5];
    const float* b   = (const float*)d_in[6];
    const float* bd  = (const float*)d_in[7];
    const float* bgt = (const float*)d_in[8];

    float* outsec = (float*)d_out;          /* [T,B,D] outputs         */
    float* hsec   = outsec + (size_t)TBD;   /* [T+1,B,D] hidden states */

    cudaFuncSetAttribute(rec_kernel,
                         cudaFuncAttributeMaxDynamicSharedMemorySize,
                         (int)SMEM_REC);

    /* h[0] = h0 */
    cudaMemcpyAsync(hsec, h0, (size_t)BD * sizeof(float),
                    cudaMemcpyDeviceToDevice, 0);

    /* big input GEMM: stash xRx into out[t], xWd into h[t+1] */
    dim3 pgrid(TT * BB / BM, 2 * DD / BN);  /* (512, 32) */
    pre_gemm_kernel<<<pgrid, 256>>>(x, Rx, Wdl, b, bd, outsec, hsec);

    /* single persistent kernel for the whole scan */
    rec_kernel<<<128, 256, SMEM_REC>>>(x, h0, Rh, Rd, bgt, outsec, hsec);
}

// round 17
// speedup vs baseline: 1.5893x; 1.5893x over previous
#include <cuda_runtime.h>
#include <math.h>

#define TT 1024
#define BB 32
#define DD 1024
#define BD (BB*DD)          /* 32768    */
#define TBD (TT*BB*DD)      /* 33554432 */

/* ---------- packed f32x2 helpers (sm_103a FFMA2) ---------- */
__device__ __forceinline__ void fma2(unsigned long long& acc,
                                     unsigned long long a,
                                     unsigned long long b) {
    asm("fma.rn.f32x2 %0, %1, %2, %0;" : "+l"(acc) : "l"(a), "l"(b));
}
__device__ __forceinline__ unsigned long long pack2(float lo, float hi) {
    unsigned long long r;
    asm("mov.b64 %0, {%1, %2};" : "=l"(r)
        : "r"(__float_as_uint(lo)), "r"(__float_as_uint(hi)));
    return r;
}
__device__ __forceinline__ float lo32(unsigned long long v) {
    return __uint_as_float((unsigned int)(v & 0xffffffffull));
}
__device__ __forceinline__ float hi32(unsigned long long v) {
    return __uint_as_float((unsigned int)(v >> 32));
}

/* transposed hidden state, double-buffered: g_hT[par][k][b], 256 KB static */
__device__ float g_hT[2][DD][BB];

/* ================= precompute GEMM (FFMA2) =================
 * C[m,n] = sum_k x[m,k]*W[n,k] + bias[n], m<32768, n<2048
 *   n <  1024 : W=R_x,     bias=b,       dst = out section    (stash xRx[t])
 *   n >= 1024 : W=W_delta, bias=b_delta, dst = h section +BD  (stash xWd[t])
 */
#define BM 64
#define BN 64
#define BKK 16
#define PAD 72

__global__ __launch_bounds__(256) void pre_gemm_kernel(
    const float* __restrict__ x,
    const float* __restrict__ Rx,
    const float* __restrict__ Wdl,
    const float* __restrict__ bias_v,
    const float* __restrict__ bias_d,
    float* __restrict__ outsec,
    float* __restrict__ hsec)
{
    __shared__ float As[BKK][PAD];
    __shared__ float Ws[BKK][PAD];

    const int m0  = blockIdx.x * BM;
    const int n0g = blockIdx.y * BN;
    const int sel = (n0g >= DD) ? 1 : 0;
    const float* __restrict__ W    = sel ? Wdl    : Rx;
    const float* __restrict__ bias = sel ? bias_d : bias_v;
    float* __restrict__ dst = sel ? (hsec + BD) : outsec;
    const int n0 = n0g & (DD - 1);

    const int tid  = threadIdx.x;
    const int lrow = tid >> 2;
    const int lk4  = (tid & 3) * 4;
    const int tx   = tid & 15;          /* n dir */
    const int ty   = tid >> 4;          /* m dir */

    unsigned long long acc2[2][4];
    #pragma unroll
    for (int p = 0; p < 2; p++)
        #pragma unroll
        for (int j = 0; j < 4; j++) acc2[p][j] = 0ull;

    const float* xa = x + (size_t)(m0 + lrow) * DD;
    const float* wa = W + (size_t)(n0 + lrow) * DD;

    for (int kk = 0; kk < DD; kk += BKK) {
        float4 a4 = *(const float4*)(xa + kk + lk4);
        float4 w4 = *(const float4*)(wa + kk + lk4);
        As[lk4 + 0][lrow] = a4.x; As[lk4 + 1][lrow] = a4.y;
        As[lk4 + 2][lrow] = a4.z; As[lk4 + 3][lrow] = a4.w;
        Ws[lk4 + 0][lrow] = w4.x; Ws[lk4 + 1][lrow] = w4.y;
        Ws[lk4 + 2][lrow] = w4.z; Ws[lk4 + 3][lrow] = w4.w;
        __syncthreads();

        #pragma unroll
        for (int k = 0; k < BKK; k++) {
            ulonglong2 a2 = *(const ulonglong2*)&As[k][ty * 4];
            float4 wf = *(const float4*)&Ws[k][tx * 4];
            unsigned long long w0 = pack2(wf.x, wf.x);
            unsigned long long w1 = pack2(wf.y, wf.y);
            unsigned long long w2 = pack2(wf.z, wf.z);
            unsigned long long w3 = pack2(wf.w, wf.w);
            fma2(acc2[0][0], a2.x, w0); fma2(acc2[0][1], a2.x, w1);
            fma2(acc2[0][2], a2.x, w2); fma2(acc2[0][3], a2.x, w3);
            fma2(acc2[1][0], a2.y, w0); fma2(acc2[1][1], a2.y, w1);
            fma2(acc2[1][2], a2.y, w2); fma2(acc2[1][3], a2.y, w3);
        }
        __syncthreads();
    }

    #pragma unroll
    for (int p = 0; p < 2; p++) {
        #pragma unroll
        for (int j = 0; j < 4; j++) {
            const int col = n0 + tx * 4 + j;
            const float bb = bias[col];
            dst[(size_t)(m0 + ty * 4 + 2 * p + 0) * DD + col] = lo32(acc2[p][j]) + bb;
            dst[(size_t)(m0 + ty * 4 + 2 * p + 1) * DD + col] = hi32(acc2[p][j]) + bb;
        }
    }
}

/* ================= persistent recurrence =================
 * 128 CTAs x 256 threads, all co-resident -> spin grid barrier safe.
 * CTA c owns d-slice [8c, 8c+8) for ALL b (lane = b, warp = k-eighth).
 * Both weight slices (8 rows of R_h + R_delta, 64 KB) live in smem,
 * loaded ONCE before the t-loop -> zero per-step weight traffic.
 * h is kept in a transposed double-buffered global array g_hT[par][k][b]
 * so the per-k h load is one coalesced 128B LDG per warp.
 */
#define SRSTRIDE 36                                  /* bank-spread pad   */
#define SMEM_W   (DD * 8 * 8)                        /* 65536 B packed w  */
#define SMEM_R   (16 * 8 * SRSTRIDE * 4)             /* 18432 B reduction */
#define SMEM_REC (SMEM_W + SMEM_R)

__device__ unsigned int g_bar = 0;
__device__ unsigned int g_gen = 0;

__device__ __forceinline__ void grid_sync() {
    __syncthreads();
    if (threadIdx.x == 0) {
        __threadfence();
        unsigned int gen = *((volatile unsigned int*)&g_gen);
        if (atomicAdd(&g_bar, 1) == 127u) {
            atomicExch(&g_bar, 0);
            __threadfence();
            atomicAdd(&g_gen, 1);
        } else {
            while (*((volatile unsigned int*)&g_gen) == gen) __nanosleep(32);
        }
        __threadfence();
    }
    __syncthreads();
}

__global__ __launch_bounds__(256, 1) void rec_kernel(
    const float* __restrict__ x,
    const float* __restrict__ h0,
    const float* __restrict__ Rh,
    const float* __restrict__ Rd,
    const float* __restrict__ bgate,
    float* __restrict__ outsec,
    float* __restrict__ hsec)
{
    extern __shared__ unsigned char smem[];
    unsigned long long* sWp = (unsigned long long*)smem;   /* [k][8] pairs */
    float* sRed = (float*)(smem + SMEM_W);

    const int cta  = blockIdx.x;
    const int d0   = cta * 8;
    const int tid  = threadIdx.x;
    const int w    = tid >> 5;
    const int lane = tid & 31;

    /* ---- stage packed weight pairs into smem (once) ---- */
    #pragma unroll
    for (int m = 0; m < 2; m++) {
        const float* W = m ? Rd : Rh;
        #pragma unroll
        for (int p = 0; p < 4; p++) {
            const float* r0 = W + (size_t)(d0 + 2 * p)     * DD;
            const float* r1 = W + (size_t)(d0 + 2 * p + 1) * DD;
            for (int k = tid; k < DD; k += 256)
                sWp[k * 8 + m * 4 + p] = pack2(r0[k], r1[k]);
        }
    }

    /* ---- init transposed h[0]: CTA c fills rows [8c, 8c+8) ---- */
    g_hT[0][8 * cta + w][lane] = h0[(size_t)lane * DD + 8 * cta + w];

    grid_sync();   /* hT[0] visible everywhere; smem weights ready locally */

    const int kb  = w * 128;
    const int edl = tid & 7;        /* epilogue d-local */
    const int eb  = tid >> 3;       /* epilogue b       */
    const float bgv = bgate[d0 + edl];

    for (int t = 0; t < TT; t++) {
        const int cur = t & 1, nxt = cur ^ 1;
        const float* hcol = &g_hT[cur][0][lane];

        unsigned long long av0 = 0, av1 = 0, av2 = 0, av3 = 0;
        unsigned long long ad0 = 0, ad1 = 0, ad2 = 0, ad3 = 0;

        /* software-pipelined k loop: prefetch 8 h values ahead (MLP=8) */
        float hbuf[8];
        #pragma unroll
        for (int i = 0; i < 8; i++) hbuf[i] = __ldg(hcol + (size_t)(kb + i) * 32);

        #pragma unroll
        for (int g = 0; g < 16; g++) {
            float hnx[8];
            if (g < 15) {
                #pragma unroll
                for (int i = 0; i < 8; i++)
                    hnx[i] = __ldg(hcol + (size_t)(kb + (g + 1) * 8 + i) * 32);
            }
            #pragma unroll
            for (int i = 0; i < 8; i++) {
                const int k = kb + g * 8 + i;
                unsigned long long h2 = pack2(hbuf[i], hbuf[i]);
                ulonglong2 wv0 = *(const ulonglong2*)&sWp[k * 8 + 0];
                ulonglong2 wv1 = *(const ulonglong2*)&sWp[k * 8 + 2];
                ulonglong2 wd0 = *(const ulonglong2*)&sWp[k * 8 + 4];
                ulonglong2 wd1 = *(const ulonglong2*)&sWp[k * 8 + 6];
                fma2(av0, wv0.x, h2); fma2(av1, wv0.y, h2);
                fma2(av2, wv1.x, h2); fma2(av3, wv1.y, h2);
                fma2(ad0, wd0.x, h2); fma2(ad1, wd0.y, h2);
                fma2(ad2, wd1.x, h2); fma2(ad3, wd1.y, h2);
            }
            if (g < 15) {
                #pragma unroll
                for (int i = 0; i < 8; i++) hbuf[i] = hnx[i];
            }
        }

        /* stage per-warp partials: sRed[(w*2+m)*8 + d][b] */
        {
            float* r0 = sRed + ((w * 2 + 0) * 8) * SRSTRIDE + lane;
            float* r1 = sRed + ((w * 2 + 1) * 8) * SRSTRIDE + lane;
            r0[0 * SRSTRIDE] = lo32(av0); r0[1 * SRSTRIDE] = hi32(av0);
            r0[2 * SRSTRIDE] = lo32(av1); r0[3 * SRSTRIDE] = hi32(av1);
            r0[4 * SRSTRIDE] = lo32(av2); r0[5 * SRSTRIDE] = hi32(av2);
            r0[6 * SRSTRIDE] = lo32(av3); r0[7 * SRSTRIDE] = hi32(av3);
            r1[0 * SRSTRIDE] = lo32(ad0); r1[1 * SRSTRIDE] = hi32(ad0);
            r1[2 * SRSTRIDE] = lo32(ad1); r1[3 * SRSTRIDE] = hi32(ad1);
            r1[4 * SRSTRIDE] = lo32(ad2); r1[5 * SRSTRIDE] = hi32(ad2);
            r1[6 * SRSTRIDE] = lo32(ad3); r1[7 * SRSTRIDE] = hi32(ad3);
        }
        __syncthreads();

        /* ---- elementwise epilogue: thread -> (b=eb, d=d0+edl) ---- */
        {
            float sumv = 0.f, sumd = 0.f;
            #pragma unroll
            for (int kw = 0; kw < 8; kw++) {
                sumv += sRed[((kw * 2 + 0) * 8 + edl) * SRSTRIDE + eb];
                sumd += sRed[((kw * 2 + 1) * 8 + edl) * SRSTRIDE + eb];
            }
            const size_t idx = (size_t)t * BD + (size_t)eb * DD + d0 + edl;

            const float v     = outsec[idx]    + sumv;   /* stash xRx + h@Rh^T */
            const float dpre  = hsec[idx + BD] + sumd;   /* stash xWd + h@Rd^T */
            const float delta = 1.f / (1.f + expf(-dpre));
            const float hp    = hsec[idx];
            const float hn    = (1.f - delta) * hp + delta * tanhf(v);
            const float z     = hn + x[idx] + bgv;
            const float sig   = 1.f / (1.f + expf(-z));

            outsec[idx]          = hn * z * sig;   /* out[t]            */
            hsec[idx + BD]       = hn;             /* h[t+1] (output)   */
            g_hT[nxt][d0 + edl][eb] = hn;          /* h[t+1] transposed */
        }

        grid_sync();   /* publish h[t+1]; also guards sRed reuse */
    }
}

extern "C" void kernel_launch(void* const* d_in, const int* in_sizes, int n_in,
                              void* d_out, int out_size)
{
    const float* x   = (const float*)d_in[0];
    const float* h0  = (const float*)d_in[1];
    const float* Rh  = (const float*)d_in[2];
    const float* Rx  = (const float*)d_in[3];
    const float* Rd  = (const float*)d_in[4];
    const float* Wdl = (const float*)d_in[5];
    const float* b   = (const float*)d_in[6];
    const float* bd  = (const float*)d_in[7];
    const float* bgt = (const float*)d_in[8];

    float* outsec = (float*)d_out;          /* [T,B,D] outputs         */
    float* hsec   = outsec + (size_t)TBD;   /* [T+1,B,D] hidden states */

    cudaFuncSetAttribute(rec_kernel,
                         cudaFuncAttributeMaxDynamicSharedMemorySize,
                         (int)SMEM_REC);

    /* h[0] = h0 */
    cudaMemcpyAsync(hsec, h0, (size_t)BD * sizeof(float),
                    cudaMemcpyDeviceToDevice, 0);

    /* big input GEMM: stash xRx into out[t], xWd into h[t+1] */
    dim3 pgrid(TT * BB / BM, 2 * DD / BN);  /* (512, 32) */
    pre_gemm_kernel<<<pgrid, 256>>>(x, Rx, Wdl, b, bd, outsec, hsec);

    /* single persistent kernel for the whole scan */
    rec_kernel<<<128, 256, SMEM_REC>>>(x, h0, Rh, Rd, bgt, outsec, hsec);
}